// round 15
// baseline (speedup 1.0000x reference)
#include <cuda_runtime.h>
#include <cuda_fp16.h>
#include <math.h>
#include <stdint.h>

// ---------------- problem constants ----------------
#define BATCH 4
#define C     256
#define NPIX  4096          // 64*64
#define GROUPS 32
#define GELEMS ((C/GROUPS)*NPIX)   // 32768 elements per group
#define EPSV  1e-5f
#define EXP_SHIFT 4.0f      // softmax fixed shift: e^(s-4); safe for s_max in (-inf, ~15]

// ---------------- scratch (device globals, no allocation) ----------------
__device__ __half g_xnh [(size_t)BATCH*C*NPIX];           // 8 MB   xn [c, n] half
__device__ __half g_qkvh[(size_t)BATCH*3*C*NPIX];         // 24 MB  qkv [o, n] half
__device__ __half g_ph  [(size_t)BATCH*NPIX*NPIX];        // 128 MB unnormalized probs half
__device__ __half g_oth [(size_t)BATCH*NPIX*C];           // 8 MB   O^T [j, c] half
__device__ __half g_wqh [3*C*C];                          // W_qkv half
__device__ __half g_woh [C*C];                            // W_out half
__device__ float  g_partial[(size_t)64*BATCH*NPIX];       // 4 MB   per-(i-slot) row sums
__device__ float  g_rowsum [(size_t)BATCH*NPIX];          // 64 KB  softmax denominators
__device__ float  g_mu  [BATCH*GROUPS];
__device__ float  g_rstd[BATCH*GROUPS];

// ---------------- helpers ----------------
#define MMA_F16(d, a, b) \
    asm volatile("mma.sync.aligned.m16n8k16.row.col.f32.f16.f16.f32 " \
        "{%0,%1,%2,%3}, {%4,%5,%6,%7}, {%8,%9}, {%0,%1,%2,%3};" \
        : "+f"((d)[0]), "+f"((d)[1]), "+f"((d)[2]), "+f"((d)[3]) \
        : "r"((a)[0]), "r"((a)[1]), "r"((a)[2]), "r"((a)[3]), \
          "r"((b)[0]), "r"((b)[1]))

#define LDSM_X4(r0, r1, r2, r3, addr) \
    asm volatile("ldmatrix.sync.aligned.m8n8.x4.shared.b16 {%0,%1,%2,%3}, [%4];" \
        : "=r"(r0), "=r"(r1), "=r"(r2), "=r"(r3) : "r"(addr))

#define LDSM_X4_T(r0, r1, r2, r3, addr) \
    asm volatile("ldmatrix.sync.aligned.m8n8.x4.trans.shared.b16 {%0,%1,%2,%3}, [%4];" \
        : "=r"(r0), "=r"(r1), "=r"(r2), "=r"(r3) : "r"(addr))

#define CPA16(dst, src) \
    asm volatile("cp.async.cg.shared.global [%0], [%1], 16;" :: "r"(dst), "l"(src))
#define CPA_COMMIT() asm volatile("cp.async.commit_group;" ::: "memory")
#define CPA_WAIT(n)  asm volatile("cp.async.wait_group %0;" :: "n"(n) : "memory")

__device__ __forceinline__ float warpRedSum(float v) {
    #pragma unroll
    for (int o = 16; o > 0; o >>= 1) v += __shfl_xor_sync(0xffffffffu, v, o);
    return v;
}

// FMA-pipe exp: e^(acc/16 - EXP_SHIFT) without MUFU.
// y = acc * (log2e/16) - 4*log2e; result = 2^y via magic-round + deg-5 poly + exponent add.
__device__ __forceinline__ float fexp_s16(float acc) {
    const float y = fmaf(acc, 0.09014067145f, -5.770780163f);
    const float r = y + 12582912.0f;                 // 1.5*2^23: round-to-nearest-int
    const int   ni = __float_as_int(r) - 0x4B400000; // integer part as int
    const float f = y - (r - 12582912.0f);           // frac in [-0.5, 0.5]
    float p = fmaf(0.0013333558f, f, 0.0096181291f);
    p = fmaf(p, f, 0.0555041087f);
    p = fmaf(p, f, 0.2402265070f);
    p = fmaf(p, f, 0.6931471806f);
    p = fmaf(p, f, 1.0f);
    return __int_as_float(__float_as_int(p) + (ni << 23));
}

// ---------------- fused group-norm stats + weight conversion ----------------
__global__ __launch_bounds__(256) void gn_stats_convw_k(const float* __restrict__ x,
                                                        const float* __restrict__ wq,
                                                        const float* __restrict__ wo) {
    if (blockIdx.x >= BATCH * GROUPS) {
        const int i4 = (blockIdx.x - BATCH * GROUPS) * 256 + threadIdx.x;  // < 65536
        const int WQ4 = 3 * C * C / 4;                                     // 49152
        float4 v;
        if (i4 < WQ4) v = reinterpret_cast<const float4*>(wq)[i4];
        else          v = reinterpret_cast<const float4*>(wo)[i4 - WQ4];
        __half2 h0 = __floats2half2_rn(v.x, v.y);
        __half2 h1 = __floats2half2_rn(v.z, v.w);
        __half* dst = (i4 < WQ4) ? (g_wqh + (size_t)i4 * 4) : (g_woh + (size_t)(i4 - WQ4) * 4);
        *reinterpret_cast<__half2*>(dst)     = h0;
        *reinterpret_cast<__half2*>(dst + 2) = h1;
        return;
    }
    const int bg = blockIdx.x;
    const float4* base = reinterpret_cast<const float4*>(x + (size_t)bg * GELEMS);
    float s = 0.f, ss = 0.f;
    for (int i = threadIdx.x; i < GELEMS / 4; i += 256) {
        float4 v = base[i];
        s  += v.x + v.y + v.z + v.w;
        ss += v.x*v.x + v.y*v.y + v.z*v.z + v.w*v.w;
    }
    __shared__ float shs[32], shss[32];
    float ws = warpRedSum(s), wss = warpRedSum(ss);
    const int lane = threadIdx.x & 31, wid = threadIdx.x >> 5;
    if (lane == 0) { shs[wid] = ws; shss[wid] = wss; }
    __syncthreads();
    if (wid == 0) {
        float a = (lane < 8) ? shs[lane] : 0.f;
        float b = (lane < 8) ? shss[lane] : 0.f;
        a = warpRedSum(a); b = warpRedSum(b);
        if (lane == 0) {
            float mean = a * (1.f / (float)GELEMS);
            float var  = b * (1.f / (float)GELEMS) - mean * mean;
            g_mu[bg] = mean;
            g_rstd[bg] = rsqrtf(var + EPSV);
        }
    }
}

// ---------------- group-norm apply (elementwise): x[c,n] fp32 -> xnh[c,n] half ----------------
__global__ __launch_bounds__(256) void gn_apply_k(const float* __restrict__ x,
                                                  const float* __restrict__ gamma,
                                                  const float* __restrict__ beta) {
    const size_t i4 = (size_t)blockIdx.x * 256 + threadIdx.x;   // float4 index
    const size_t e  = i4 * 4;
    const int c  = (int)((e >> 12) & (C - 1));                  // NPIX = 4096 = 2^12
    const int bg = (int)(e >> 15);                              // per group: 8ch*4096 = 32768 = 2^15
    const float sc = gamma[c] * g_rstd[bg];
    const float sh = beta[c] - g_mu[bg] * sc;
    float4 v = reinterpret_cast<const float4*>(x)[i4];
    __half* dst = g_xnh + e;
    *reinterpret_cast<__half2*>(dst) =
        __floats2half2_rn(fmaf(v.x, sc, sh), fmaf(v.y, sc, sh));
    *reinterpret_cast<__half2*>(dst + 2) =
        __floats2half2_rn(fmaf(v.z, sc, sh), fmaf(v.w, sc, sh));
}

// ---------------- rowsum reduce: partial[64][B*N] -> rowsum[B*N] ----------------
__global__ __launch_bounds__(256) void reduce_rowsum_k() {
    const int idx = blockIdx.x * 256 + threadIdx.x;           // < BATCH*NPIX
    float s = 0.f;
    #pragma unroll
    for (int i = 0; i < 64; i++)
        s += g_partial[(size_t)i * (BATCH * NPIX) + idx];
    g_rowsum[idx] = s;
}

// ---------------- fp16 tensor GEMM, 5-stage cp.async + ldmatrix(.trans) ----------------
// D[m,n] = sum_k A(m,k) * B(n,k).
//   AT=false: A stored [m][k] k-contig (lda = k-stride). AT=true: A stored [k][m] m-contig (lda = row stride).
//   BT likewise for B with n<->m.
// Epilogue MODE: 0 fp32+bias | 1 half+bias | 2 half exp(D/16-SHIFT)+rowsum partials | 3 half D/rowsum.
// Block tile 128x128, KTILE=32, 8 warps (4m x 2n), warp tile 32x64. 2 CTAs/SM.
#define HKT    32
#define NSTR   40                            // non-trans row stride (halves)
#define TSTR   136                           // trans row stride (halves)
#define STAGES 5

template<int MODE, bool AT, bool BT>
__global__ __launch_bounds__(256)
void hgemm_k(const __half* __restrict__ A, const __half* __restrict__ B,
             const float* __restrict__ bias, const float* __restrict__ aux,
             float* __restrict__ auxw, void* __restrict__ Cg,
             int lda, int ldb, int ldc, int K,
             long long sA, long long sB, long long sC)
{
    constexpr int A_TH  = AT ? (HKT * TSTR) : (128 * NSTR);   // halves per A tile
    constexpr int B_TH  = BT ? (HKT * TSTR) : (128 * NSTR);
    constexpr int STG_H = A_TH + B_TH;

    extern __shared__ __half sm[];
    const uint32_t smem_b = (uint32_t)__cvta_generic_to_shared(sm);

    const int t = threadIdx.x, wid = t >> 5, lane = t & 31;
    const int g = lane >> 2, tq = lane & 3;
    const int wm = (wid >> 1) * 32;         // 4 warps along m
    const int wn = (wid & 1) * 64;          // 2 warps along n
    const int bm = blockIdx.y * 128;
    const int bn = blockIdx.x * 128;
    A += (long long)blockIdx.z * sA + (AT ? (long long)bm : (long long)bm * lda);
    B += (long long)blockIdx.z * sB + (BT ? (long long)bn : (long long)bn * ldb);

    // per-thread cp.async source/dest geometry
    const int nt_r = t >> 2, nt_c = (t & 3) << 3;   // non-trans: 2 iters of 64 rows x 4 chunks
    const int tr_r = t >> 4, tr_c = (t & 15) << 3;  // trans: 2 iters of 16 rows x 16 chunks

    // ldmatrix per-lane base offsets (halves, within a stage)
    uint32_t a_off[2], b_off[4];
    #pragma unroll
    for (int mf = 0; mf < 2; mf++) {
        if (AT) // rows k: (L&7)+((L&16)?8:0); col m: +((L&8)?8:0)
            a_off[mf] = (uint32_t)(((lane & 7) + ((lane & 16) ? 8 : 0)) * TSTR
                                   + wm + mf * 16 + ((lane & 8) ? 8 : 0));
        else    // rows m: (L&15); k-half: (L>>4)*8
            a_off[mf] = (uint32_t)((wm + mf * 16 + (lane & 15)) * NSTR + ((lane >> 4) * 8));
    }
    #pragma unroll
    for (int p = 0; p < 4; p++) {
        if (BT) // rows k: (L&7)+((L&8)?8:0); col n: +((L&16)?8:0)
            b_off[p] = (uint32_t)(((lane & 7) + ((lane & 8) ? 8 : 0)) * TSTR
                                  + wn + p * 16 + ((lane & 16) ? 8 : 0)) + A_TH;
        else    // rows n: p*16 + ((L&16)?8:0)+(L&7); k-half: (L&8)?8:0
            b_off[p] = (uint32_t)((wn + p * 16 + ((lane & 16) ? 8 : 0) + (lane & 7)) * NSTR
                                  + ((lane & 8) ? 8 : 0)) + A_TH;
    }

    float acc[2][8][4];
    #pragma unroll
    for (int i = 0; i < 2; i++)
        #pragma unroll
        for (int j = 0; j < 8; j++)
            #pragma unroll
            for (int r = 0; r < 4; r++) acc[i][j][r] = 0.f;

    const int T = K / HKT;

    // stage loader
    auto load_stage = [&](int s, int k0) {
        const uint32_t sb = smem_b + (uint32_t)s * (STG_H * 2);
        #pragma unroll
        for (int i = 0; i < 2; i++) {
            if (AT) {
                const int r = tr_r + 16 * i;
                CPA16(sb + (uint32_t)(r * TSTR + tr_c) * 2, &A[(long long)(k0 + r) * lda + tr_c]);
            } else {
                const int r = nt_r + 64 * i;
                CPA16(sb + (uint32_t)(r * NSTR + nt_c) * 2, &A[(long long)r * lda + k0 + nt_c]);
            }
            if (BT) {
                const int r = tr_r + 16 * i;
                CPA16(sb + (uint32_t)(A_TH + r * TSTR + tr_c) * 2, &B[(long long)(k0 + r) * ldb + tr_c]);
            } else {
                const int r = nt_r + 64 * i;
                CPA16(sb + (uint32_t)(A_TH + r * NSTR + nt_c) * 2, &B[(long long)r * ldb + k0 + nt_c]);
            }
        }
        CPA_COMMIT();
    };

    // prologue: stages 0..STAGES-2 (clamped to T)
    #pragma unroll
    for (int s = 0; s < STAGES - 1; s++)
        if (s < T) load_stage(s, s * HKT);

    int slot = 0;
    for (int kt = 0; kt < T; kt++) {
        CPA_WAIT(STAGES - 2);
        __syncthreads();

        if (kt + STAGES - 1 < T) {
            const int ws = (slot + STAGES - 1 >= STAGES) ? slot + STAGES - 1 - STAGES : slot + STAGES - 1;
            load_stage(ws, (kt + STAGES - 1) * HKT);
        }

        // compute on slot
        {
            const uint32_t sbase = smem_b + (uint32_t)slot * (STG_H * 2);
            #pragma unroll
            for (int ks = 0; ks < HKT; ks += 16) {
                uint32_t af[2][4], bf[8][2];
                #pragma unroll
                for (int mf = 0; mf < 2; mf++) {
                    const uint32_t ad = sbase + (a_off[mf] + (AT ? ks * TSTR : ks)) * 2;
                    if (AT) { LDSM_X4_T(af[mf][0], af[mf][1], af[mf][2], af[mf][3], ad); }
                    else    { LDSM_X4  (af[mf][0], af[mf][1], af[mf][2], af[mf][3], ad); }
                }
                #pragma unroll
                for (int p = 0; p < 4; p++) {
                    const uint32_t bd = sbase + (b_off[p] + (BT ? ks * TSTR : ks)) * 2;
                    if (BT) { LDSM_X4_T(bf[2*p][0], bf[2*p][1], bf[2*p+1][0], bf[2*p+1][1], bd); }
                    else    { LDSM_X4  (bf[2*p][0], bf[2*p][1], bf[2*p+1][0], bf[2*p+1][1], bd); }
                }
                #pragma unroll
                for (int mf = 0; mf < 2; mf++)
                    #pragma unroll
                    for (int nf = 0; nf < 8; nf++)
                        MMA_F16(acc[mf][nf], af[mf], bf[nf]);
            }
        }
        slot = (slot + 1 == STAGES) ? 0 : slot + 1;
    }

    // ---- epilogue ----
    float psum[2][2];
    if (MODE == 2) {
        psum[0][0] = psum[0][1] = psum[1][0] = psum[1][1] = 0.f;
        #pragma unroll
        for (int mf = 0; mf < 2; mf++)
            #pragma unroll
            for (int nf = 0; nf < 8; nf++)
                #pragma unroll
                for (int r = 0; r < 4; r++) {
                    const float e = fexp_s16(acc[mf][nf][r]);   // FMA-pipe exp(D/16 - SHIFT)
                    acc[mf][nf][r] = e;
                    psum[mf][r >> 1] += e;
                }
    }

    #pragma unroll
    for (int mf = 0; mf < 2; mf++)
        #pragma unroll
        for (int h = 0; h < 2; h++) {
            const long long row = bm + wm + mf * 16 + g + 8 * h;
            float bv = 0.f, scl = 1.f;
            if (MODE == 0 || MODE == 1) bv = __ldg(&bias[row]);
            if (MODE == 3) scl = 1.f / __ldg(&aux[(size_t)blockIdx.z * NPIX + row]);
            #pragma unroll
            for (int nf = 0; nf < 8; nf++) {
                const long long col = bn + wn + nf * 8 + 2 * tq;
                float vx = acc[mf][nf][2 * h];
                float vy = acc[mf][nf][2 * h + 1];
                if (MODE == 0 || MODE == 1) { vx += bv; vy += bv; }
                if (MODE == 3)              { vx *= scl; vy *= scl; }
                if (MODE == 0) {
                    float* Cf = (float*)Cg + (long long)blockIdx.z * sC;
                    *reinterpret_cast<float2*>(&Cf[row * ldc + col]) = make_float2(vx, vy);
                } else {
                    __half* Ch = (__half*)Cg + (long long)blockIdx.z * sC;
                    *reinterpret_cast<__half2*>(&Ch[row * ldc + col]) = __floats2half2_rn(vx, vy);
                }
            }
        }

    if (MODE == 2) {
        #pragma unroll
        for (int mf = 0; mf < 2; mf++)
            #pragma unroll
            for (int h = 0; h < 2; h++) {
                float s = psum[mf][h];
                s += __shfl_xor_sync(0xffffffffu, s, 1);
                s += __shfl_xor_sync(0xffffffffu, s, 2);
                if (tq == 0) {
                    const int slot2 = blockIdx.x * 2 + (wid & 1);   // 64 slots
                    const long long row = bm + wm + mf * 16 + g + 8 * h;
                    auxw[(size_t)slot2 * (BATCH * NPIX) + (size_t)blockIdx.z * NPIX + row] = s;
                }
            }
    }
}

// smem bytes per instantiation
static constexpr int smem_bytes(bool AT, bool BT) {
    return STAGES * ((AT ? HKT * TSTR : 128 * NSTR) + (BT ? HKT * TSTR : 128 * NSTR)) * 2;
}

// ---------------- launch ----------------
extern "C" void kernel_launch(void* const* d_in, const int* in_sizes, int n_in,
                              void* d_out, int out_size) {
    (void)in_sizes; (void)n_in; (void)out_size;
    const float* x        = (const float*)d_in[0];
    const float* gn_gamma = (const float*)d_in[1];
    const float* gn_beta  = (const float*)d_in[2];
    const float* w_qkv    = (const float*)d_in[3];
    const float* b_qkv    = (const float*)d_in[4];
    const float* w_out    = (const float*)d_in[5];
    const float* b_out    = (const float*)d_in[6];
    float* out = (float*)d_out;

    __half *xnh, *qkvh, *ph, *oth, *wqh, *woh;
    float *partial, *rowsum;
    cudaGetSymbolAddress((void**)&xnh,     g_xnh);
    cudaGetSymbolAddress((void**)&qkvh,    g_qkvh);
    cudaGetSymbolAddress((void**)&ph,      g_ph);
    cudaGetSymbolAddress((void**)&oth,     g_oth);
    cudaGetSymbolAddress((void**)&wqh,     g_wqh);
    cudaGetSymbolAddress((void**)&woh,     g_woh);
    cudaGetSymbolAddress((void**)&partial, g_partial);
    cudaGetSymbolAddress((void**)&rowsum,  g_rowsum);

    constexpr int SM_QKV = smem_bytes(false, true);    // 94720
    constexpr int SM_SC  = smem_bytes(true,  true);    // 87040
    constexpr int SM_NN  = smem_bytes(false, false);   // 102400
    cudaFuncSetAttribute(hgemm_k<1, false, true >, cudaFuncAttributeMaxDynamicSharedMemorySize, SM_QKV);
    cudaFuncSetAttribute(hgemm_k<2, true,  true >, cudaFuncAttributeMaxDynamicSharedMemorySize, SM_SC);
    cudaFuncSetAttribute(hgemm_k<3, false, false>, cudaFuncAttributeMaxDynamicSharedMemorySize, SM_NN);
    cudaFuncSetAttribute(hgemm_k<0, false, false>, cudaFuncAttributeMaxDynamicSharedMemorySize, SM_NN);

    // 1) group-norm stats + weight conversion (fused launch)
    gn_stats_convw_k<<<BATCH * GROUPS + 256, 256>>>(x, w_qkv, w_out);

    // 2) GN apply (elementwise) -> xnh [c, n] half
    gn_apply_k<<<(BATCH * C * NPIX) / (4 * 256), 256>>>(x, gn_gamma, gn_beta);

    // 3) qkv[o,n] half = Wqkv[o,c] . xn[c,n] + b_qkv   (B trans-loaded)
    hgemm_k<1, false, true><<<dim3(NPIX / 128, (3 * C) / 128, BATCH), 256, SM_QKV>>>(
        wqh, xnh, b_qkv, nullptr, nullptr, qkvh, C, NPIX, NPIX, C,
        0LL, (long long)C * NPIX, (long long)3 * C * NPIX);

    // 4) scores+exp: Ph[j,i] = exp(Q[:,j].K[:,i]/16 - SHIFT); partial row sums
    //    (A = Q [c,j] trans, B = K [c,i] trans, straight from qkv)
    hgemm_k<2, true, true><<<dim3(NPIX / 128, NPIX / 128, BATCH), 256, SM_SC>>>(
        qkvh, qkvh + (size_t)C * NPIX, nullptr, nullptr, partial, ph,
        NPIX, NPIX, NPIX, C,
        (long long)3 * C * NPIX, (long long)3 * C * NPIX, (long long)NPIX * NPIX);

    // 5) rowsum[b,j] = sum of 64 partials
    reduce_rowsum_k<<<BATCH * NPIX / 256, 256>>>();

    // 6) O^T[j,c] half = (Ph[j,:] . V[c,:]^T) / rowsum[b,j]   (K = 4096)
    hgemm_k<3, false, false><<<dim3(C / 128, NPIX / 128, BATCH), 256, SM_NN>>>(
        ph, qkvh + (size_t)2 * C * NPIX, nullptr, rowsum, nullptr, oth,
        NPIX, NPIX, C, NPIX,
        (long long)NPIX * NPIX, (long long)3 * C * NPIX, (long long)NPIX * C);

    // 7) out[o,j] fp32 = Wout[o,c] . OT[j,c]^T + b_out
    hgemm_k<0, false, false><<<dim3(NPIX / 128, C / 128, BATCH), 256, SM_NN>>>(
        woh, oth, b_out, nullptr, nullptr, out, C, C, NPIX, C,
        0LL, (long long)NPIX * C, (long long)C * NPIX);
}

// round 17
// speedup vs baseline: 1.0412x; 1.0412x over previous
#include <cuda_runtime.h>
#include <cuda_fp16.h>
#include <math.h>
#include <stdint.h>

// ---------------- problem constants ----------------
#define BATCH 4
#define C     256
#define NPIX  4096          // 64*64
#define GROUPS 32
#define GELEMS ((C/GROUPS)*NPIX)   // 32768 elements per group
#define EPSV  1e-5f
#define EXP_SHIFT 4.0f      // softmax fixed shift: e^(s-4); safe for s_max in (-inf, ~15]

// ---------------- scratch (device globals, no allocation) ----------------
__device__ __half g_xnh [(size_t)BATCH*C*NPIX];           // 8 MB   xn [c, n] half
__device__ __half g_qkvh[(size_t)BATCH*3*C*NPIX];         // 24 MB  qkv [o, n] half
__device__ __half g_ph  [(size_t)BATCH*NPIX*NPIX];        // 128 MB unnormalized probs half
__device__ __half g_oth [(size_t)BATCH*NPIX*C];           // 8 MB   O^T [j, c] half
__device__ __half g_wqh [3*C*C];                          // W_qkv half
__device__ __half g_woh [C*C];                            // W_out half
__device__ float  g_partial[(size_t)64*BATCH*NPIX];       // 4 MB   per-(i-slot) row sums
__device__ float  g_mu  [BATCH*GROUPS];
__device__ float  g_rstd[BATCH*GROUPS];

// ---------------- helpers ----------------
#define MMA_F16(d, a, b) \
    asm volatile("mma.sync.aligned.m16n8k16.row.col.f32.f16.f16.f32 " \
        "{%0,%1,%2,%3}, {%4,%5,%6,%7}, {%8,%9}, {%0,%1,%2,%3};" \
        : "+f"((d)[0]), "+f"((d)[1]), "+f"((d)[2]), "+f"((d)[3]) \
        : "r"((a)[0]), "r"((a)[1]), "r"((a)[2]), "r"((a)[3]), \
          "r"((b)[0]), "r"((b)[1]))

#define LDSM_X4(r0, r1, r2, r3, addr) \
    asm volatile("ldmatrix.sync.aligned.m8n8.x4.shared.b16 {%0,%1,%2,%3}, [%4];" \
        : "=r"(r0), "=r"(r1), "=r"(r2), "=r"(r3) : "r"(addr))

#define LDSM_X4_T(r0, r1, r2, r3, addr) \
    asm volatile("ldmatrix.sync.aligned.m8n8.x4.trans.shared.b16 {%0,%1,%2,%3}, [%4];" \
        : "=r"(r0), "=r"(r1), "=r"(r2), "=r"(r3) : "r"(addr))

#define CPA16(dst, src) \
    asm volatile("cp.async.cg.shared.global [%0], [%1], 16;" :: "r"(dst), "l"(src))
#define CPA_COMMIT() asm volatile("cp.async.commit_group;" ::: "memory")
#define CPA_WAIT(n)  asm volatile("cp.async.wait_group %0;" :: "n"(n) : "memory")

__device__ __forceinline__ float warpRedSum(float v) {
    #pragma unroll
    for (int o = 16; o > 0; o >>= 1) v += __shfl_xor_sync(0xffffffffu, v, o);
    return v;
}

// ---------------- fused group-norm stats + weight conversion ----------------
__global__ __launch_bounds__(256) void gn_stats_convw_k(const float* __restrict__ x,
                                                        const float* __restrict__ wq,
                                                        const float* __restrict__ wo) {
    if (blockIdx.x >= BATCH * GROUPS) {
        const int i4 = (blockIdx.x - BATCH * GROUPS) * 256 + threadIdx.x;  // < 65536
        const int WQ4 = 3 * C * C / 4;                                     // 49152
        float4 v;
        if (i4 < WQ4) v = reinterpret_cast<const float4*>(wq)[i4];
        else          v = reinterpret_cast<const float4*>(wo)[i4 - WQ4];
        __half2 h0 = __floats2half2_rn(v.x, v.y);
        __half2 h1 = __floats2half2_rn(v.z, v.w);
        __half* dst = (i4 < WQ4) ? (g_wqh + (size_t)i4 * 4) : (g_woh + (size_t)(i4 - WQ4) * 4);
        *reinterpret_cast<__half2*>(dst)     = h0;
        *reinterpret_cast<__half2*>(dst + 2) = h1;
        return;
    }
    const int bg = blockIdx.x;
    const float4* base = reinterpret_cast<const float4*>(x + (size_t)bg * GELEMS);
    float s = 0.f, ss = 0.f;
    for (int i = threadIdx.x; i < GELEMS / 4; i += 256) {
        float4 v = base[i];
        s  += v.x + v.y + v.z + v.w;
        ss += v.x*v.x + v.y*v.y + v.z*v.z + v.w*v.w;
    }
    __shared__ float shs[32], shss[32];
    float ws = warpRedSum(s), wss = warpRedSum(ss);
    const int lane = threadIdx.x & 31, wid = threadIdx.x >> 5;
    if (lane == 0) { shs[wid] = ws; shss[wid] = wss; }
    __syncthreads();
    if (wid == 0) {
        float a = (lane < 8) ? shs[lane] : 0.f;
        float b = (lane < 8) ? shss[lane] : 0.f;
        a = warpRedSum(a); b = warpRedSum(b);
        if (lane == 0) {
            float mean = a * (1.f / (float)GELEMS);
            float var  = b * (1.f / (float)GELEMS) - mean * mean;
            g_mu[bg] = mean;
            g_rstd[bg] = rsqrtf(var + EPSV);
        }
    }
}

// ---------------- group-norm apply (elementwise): x[c,n] fp32 -> xnh[c,n] half ----------------
__global__ __launch_bounds__(256) void gn_apply_k(const float* __restrict__ x,
                                                  const float* __restrict__ gamma,
                                                  const float* __restrict__ beta) {
    const size_t i4 = (size_t)blockIdx.x * 256 + threadIdx.x;   // float4 index
    const size_t e  = i4 * 4;
    const int c  = (int)((e >> 12) & (C - 1));                  // NPIX = 4096 = 2^12
    const int bg = (int)(e >> 15);                              // per group: 8ch*4096 = 32768 = 2^15
    const float sc = gamma[c] * g_rstd[bg];
    const float sh = beta[c] - g_mu[bg] * sc;
    float4 v = reinterpret_cast<const float4*>(x)[i4];
    __half* dst = g_xnh + e;
    *reinterpret_cast<__half2*>(dst) =
        __floats2half2_rn(fmaf(v.x, sc, sh), fmaf(v.y, sc, sh));
    *reinterpret_cast<__half2*>(dst + 2) =
        __floats2half2_rn(fmaf(v.z, sc, sh), fmaf(v.w, sc, sh));
}

// ---------------- fp16 tensor GEMM, cp.async pipeline + ldmatrix(.trans) ----------------
// D[m,n] = sum_k A(m,k) * B(n,k).
//   AT=false: A stored [m][k] k-contig. AT=true: A stored [k][m] m-contig. BT likewise.
// MODE: 0 fp32+bias | 1 half+bias | 2 half exp(D/16-SHIFT)+rowsum partials | 3 half D/rowsum(partials)
// KT = k per stage (trans operands any multiple of 16; non-trans requires 32).
// NS = pipeline stages. Block tile 128x128, 8 warps (4m x 2n). 2 CTAs/SM.
#define NSTR   40                            // non-trans row stride (halves)
#define TSTR   136                           // trans row stride (halves)

template<int MODE, bool AT, bool BT, int KT, int NS>
__global__ __launch_bounds__(256)
void hgemm_k(const __half* __restrict__ A, const __half* __restrict__ B,
             const float* __restrict__ bias, const float* __restrict__ aux,
             float* __restrict__ auxw, void* __restrict__ Cg,
             int lda, int ldb, int ldc, int K,
             long long sA, long long sB, long long sC)
{
    static_assert(AT || KT == 32, "non-trans A requires KT=32");
    static_assert(BT || KT == 32, "non-trans B requires KT=32");
    constexpr int A_TH  = AT ? (KT * TSTR) : (128 * NSTR);   // halves per A tile
    constexpr int B_TH  = BT ? (KT * TSTR) : (128 * NSTR);
    constexpr int STG_H = A_TH + B_TH;

    extern __shared__ __half sm[];
    __shared__ float rs[128];               // MODE 3: per-row 1/rowsum
    const uint32_t smem_b = (uint32_t)__cvta_generic_to_shared(sm);

    const int t = threadIdx.x, wid = t >> 5, lane = t & 31;
    const int g = lane >> 2, tq = lane & 3;
    const int wm = (wid >> 1) * 32;         // 4 warps along m
    const int wn = (wid & 1) * 64;          // 2 warps along n
    const int bm = blockIdx.y * 128;
    const int bn = blockIdx.x * 128;
    A += (long long)blockIdx.z * sA + (AT ? (long long)bm : (long long)bm * lda);
    B += (long long)blockIdx.z * sB + (BT ? (long long)bn : (long long)bn * ldb);

    // MODE 3: compute 1/rowsum for this CTA's 128 rows from the 64 partial slices.
    if (MODE == 3 && t < 128) {
        const float* pp = aux + (size_t)blockIdx.z * NPIX + bm + t;
        float s = 0.f;
        #pragma unroll
        for (int i = 0; i < 64; i++)
            s += pp[(size_t)i * (BATCH * NPIX)];
        rs[t] = 1.f / s;
    }

    // per-thread cp.async source/dest geometry
    const int nt_r = t >> 2, nt_c = (t & 3) << 3;   // non-trans: 2 iters of 64 rows x 4 chunks (KT=32)
    const int tr_r = t >> 4, tr_c = (t & 15) << 3;  // trans: KT/16 iters of 16 rows x 16 chunks

    // ldmatrix per-lane base offsets (halves, within a stage)
    uint32_t a_off[2], b_off[4];
    #pragma unroll
    for (int mf = 0; mf < 2; mf++) {
        if (AT) // rows k: (L&7)+((L&16)?8:0); col m: +((L&8)?8:0)
            a_off[mf] = (uint32_t)(((lane & 7) + ((lane & 16) ? 8 : 0)) * TSTR
                                   + wm + mf * 16 + ((lane & 8) ? 8 : 0));
        else    // rows m: (L&15); k-half: (L>>4)*8
            a_off[mf] = (uint32_t)((wm + mf * 16 + (lane & 15)) * NSTR + ((lane >> 4) * 8));
    }
    #pragma unroll
    for (int p = 0; p < 4; p++) {
        if (BT) // rows k: (L&7)+((L&8)?8:0); col n: +((L&16)?8:0)
            b_off[p] = (uint32_t)(((lane & 7) + ((lane & 8) ? 8 : 0)) * TSTR
                                  + wn + p * 16 + ((lane & 16) ? 8 : 0)) + A_TH;
        else    // rows n: p*16 + ((L&16)?8:0)+(L&7); k-half: (L&8)?8:0
            b_off[p] = (uint32_t)((wn + p * 16 + ((lane & 16) ? 8 : 0) + (lane & 7)) * NSTR
                                  + ((lane & 8) ? 8 : 0)) + A_TH;
    }

    float acc[2][8][4];
    #pragma unroll
    for (int i = 0; i < 2; i++)
        #pragma unroll
        for (int j = 0; j < 8; j++)
            #pragma unroll
            for (int r = 0; r < 4; r++) acc[i][j][r] = 0.f;

    const int T = K / KT;

    // stage loader
    auto load_stage = [&](int s, int k0) {
        const uint32_t sb = smem_b + (uint32_t)s * (STG_H * 2);
        if (AT) {
            #pragma unroll
            for (int i = 0; i < KT / 16; i++) {
                const int r = tr_r + 16 * i;
                CPA16(sb + (uint32_t)(r * TSTR + tr_c) * 2, &A[(long long)(k0 + r) * lda + tr_c]);
            }
        } else {
            #pragma unroll
            for (int i = 0; i < 2; i++) {
                const int r = nt_r + 64 * i;
                CPA16(sb + (uint32_t)(r * NSTR + nt_c) * 2, &A[(long long)r * lda + k0 + nt_c]);
            }
        }
        if (BT) {
            #pragma unroll
            for (int i = 0; i < KT / 16; i++) {
                const int r = tr_r + 16 * i;
                CPA16(sb + (uint32_t)(A_TH + r * TSTR + tr_c) * 2, &B[(long long)(k0 + r) * ldb + tr_c]);
            }
        } else {
            #pragma unroll
            for (int i = 0; i < 2; i++) {
                const int r = nt_r + 64 * i;
                CPA16(sb + (uint32_t)(A_TH + r * NSTR + nt_c) * 2, &B[(long long)r * ldb + k0 + nt_c]);
            }
        }
        CPA_COMMIT();
    };

    // prologue: stages 0..NS-2 (clamped to T)
    #pragma unroll
    for (int s = 0; s < NS - 1; s++)
        if (s < T) load_stage(s, s * KT);

    int slot = 0;
    for (int kt = 0; kt < T; kt++) {
        CPA_WAIT(NS - 2);
        __syncthreads();

        if (kt + NS - 1 < T) {
            const int ws = (slot + NS - 1 >= NS) ? slot + NS - 1 - NS : slot + NS - 1;
            load_stage(ws, (kt + NS - 1) * KT);
        }

        // compute on slot
        {
            const uint32_t sbase = smem_b + (uint32_t)slot * (STG_H * 2);
            #pragma unroll
            for (int ks = 0; ks < KT; ks += 16) {
                uint32_t af[2][4], bf[8][2];
                #pragma unroll
                for (int mf = 0; mf < 2; mf++) {
                    const uint32_t ad = sbase + (a_off[mf] + (AT ? ks * TSTR : ks)) * 2;
                    if (AT) { LDSM_X4_T(af[mf][0], af[mf][1], af[mf][2], af[mf][3], ad); }
                    else    { LDSM_X4  (af[mf][0], af[mf][1], af[mf][2], af[mf][3], ad); }
                }
                #pragma unroll
                for (int p = 0; p < 4; p++) {
                    const uint32_t bd = sbase + (b_off[p] + (BT ? ks * TSTR : ks)) * 2;
                    if (BT) { LDSM_X4_T(bf[2*p][0], bf[2*p][1], bf[2*p+1][0], bf[2*p+1][1], bd); }
                    else    { LDSM_X4  (bf[2*p][0], bf[2*p][1], bf[2*p+1][0], bf[2*p+1][1], bd); }
                }
                #pragma unroll
                for (int mf = 0; mf < 2; mf++)
                    #pragma unroll
                    for (int nf = 0; nf < 8; nf++)
                        MMA_F16(acc[mf][nf], af[mf], bf[nf]);
            }
        }
        slot = (slot + 1 == NS) ? 0 : slot + 1;
    }

    // ---- epilogue ----
    float psum[2][2];
    if (MODE == 2) {
        psum[0][0] = psum[0][1] = psum[1][0] = psum[1][1] = 0.f;
        #pragma unroll
        for (int mf = 0; mf < 2; mf++)
            #pragma unroll
            for (int nf = 0; nf < 8; nf++)
                #pragma unroll
                for (int r = 0; r < 4; r++) {
                    const float e = __expf(fmaf(acc[mf][nf][r], 0.0625f, -EXP_SHIFT));
                    acc[mf][nf][r] = e;
                    psum[mf][r >> 1] += e;
                }
    }

    #pragma unroll
    for (int mf = 0; mf < 2; mf++)
        #pragma unroll
        for (int h = 0; h < 2; h++) {
            const int rloc = wm + mf * 16 + g + 8 * h;
            const long long row = bm + rloc;
            float bv = 0.f, scl = 1.f;
            if (MODE == 0 || MODE == 1) bv = __ldg(&bias[row]);
            if (MODE == 3) scl = rs[rloc];
            #pragma unroll
            for (int nf = 0; nf < 8; nf++) {
                const long long col = bn + wn + nf * 8 + 2 * tq;
                float vx = acc[mf][nf][2 * h];
                float vy = acc[mf][nf][2 * h + 1];
                if (MODE == 0 || MODE == 1) { vx += bv; vy += bv; }
                if (MODE == 3)              { vx *= scl; vy *= scl; }
                if (MODE == 0) {
                    float* Cf = (float*)Cg + (long long)blockIdx.z * sC;
                    *reinterpret_cast<float2*>(&Cf[row * ldc + col]) = make_float2(vx, vy);
                } else {
                    __half* Ch = (__half*)Cg + (long long)blockIdx.z * sC;
                    *reinterpret_cast<__half2*>(&Ch[row * ldc + col]) = __floats2half2_rn(vx, vy);
                }
            }
        }

    if (MODE == 2) {
        #pragma unroll
        for (int mf = 0; mf < 2; mf++)
            #pragma unroll
            for (int h = 0; h < 2; h++) {
                float s = psum[mf][h];
                s += __shfl_xor_sync(0xffffffffu, s, 1);
                s += __shfl_xor_sync(0xffffffffu, s, 2);
                if (tq == 0) {
                    const int slot2 = blockIdx.x * 2 + (wid & 1);   // 64 slots
                    const long long row = bm + wm + mf * 16 + g + 8 * h;
                    auxw[(size_t)slot2 * (BATCH * NPIX) + (size_t)blockIdx.z * NPIX + row] = s;
                }
            }
    }
}

// smem bytes per instantiation
static constexpr int smem_bytes(bool AT, bool BT, int KT, int NS) {
    return NS * ((AT ? KT * TSTR : 128 * NSTR) + (BT ? KT * TSTR : 128 * NSTR)) * 2;
}

// ---------------- launch ----------------
extern "C" void kernel_launch(void* const* d_in, const int* in_sizes, int n_in,
                              void* d_out, int out_size) {
    (void)in_sizes; (void)n_in; (void)out_size;
    const float* x        = (const float*)d_in[0];
    const float* gn_gamma = (const float*)d_in[1];
    const float* gn_beta  = (const float*)d_in[2];
    const float* w_qkv    = (const float*)d_in[3];
    const float* b_qkv    = (const float*)d_in[4];
    const float* w_out    = (const float*)d_in[5];
    const float* b_out    = (const float*)d_in[6];
    float* out = (float*)d_out;

    __half *xnh, *qkvh, *ph, *oth, *wqh, *woh;
    float *partial;
    cudaGetSymbolAddress((void**)&xnh,     g_xnh);
    cudaGetSymbolAddress((void**)&qkvh,    g_qkvh);
    cudaGetSymbolAddress((void**)&ph,      g_ph);
    cudaGetSymbolAddress((void**)&oth,     g_oth);
    cudaGetSymbolAddress((void**)&wqh,     g_wqh);
    cudaGetSymbolAddress((void**)&woh,     g_woh);
    cudaGetSymbolAddress((void**)&partial, g_partial);

    constexpr int SM_QKV = smem_bytes(false, true,  32, 5);   // 94720
    constexpr int SM_SC  = smem_bytes(true,  true,  64, 3);   // 104448
    constexpr int SM_NN  = smem_bytes(false, false, 32, 5);   // 102400
    cudaFuncSetAttribute(hgemm_k<1, false, true,  32, 5>, cudaFuncAttributeMaxDynamicSharedMemorySize, SM_QKV);
    cudaFuncSetAttribute(hgemm_k<2, true,  true,  64, 3>, cudaFuncAttributeMaxDynamicSharedMemorySize, SM_SC);
    cudaFuncSetAttribute(hgemm_k<3, false, false, 32, 5>, cudaFuncAttributeMaxDynamicSharedMemorySize, SM_NN);
    cudaFuncSetAttribute(hgemm_k<0, false, false, 32, 5>, cudaFuncAttributeMaxDynamicSharedMemorySize, SM_NN);

    // 1) group-norm stats + weight conversion (fused launch)
    gn_stats_convw_k<<<BATCH * GROUPS + 256, 256>>>(x, w_qkv, w_out);

    // 2) GN apply (elementwise) -> xnh [c, n] half
    gn_apply_k<<<(BATCH * C * NPIX) / (4 * 256), 256>>>(x, gn_gamma, gn_beta);

    // 3) qkv[o,n] half = Wqkv[o,c] . xn[c,n] + b_qkv   (B trans-loaded)
    hgemm_k<1, false, true, 32, 5><<<dim3(NPIX / 128, (3 * C) / 128, BATCH), 256, SM_QKV>>>(
        wqh, xnh, b_qkv, nullptr, nullptr, qkvh, C, NPIX, NPIX, C,
        0LL, (long long)C * NPIX, (long long)3 * C * NPIX);

    // 4) scores+exp: Ph[j,i] = exp(Q[:,j].K[:,i]/16 - SHIFT); partial row sums
    //    (A = Q [c,j] trans, B = K [c,i] trans, straight from qkv; KT=64, 3 stages)
    hgemm_k<2, true, true, 64, 3><<<dim3(NPIX / 128, NPIX / 128, BATCH), 256, SM_SC>>>(
        qkvh, qkvh + (size_t)C * NPIX, nullptr, nullptr, partial, ph,
        NPIX, NPIX, NPIX, C,
        (long long)3 * C * NPIX, (long long)3 * C * NPIX, (long long)NPIX * NPIX);

    // 5) O^T[j,c] half = (Ph[j,:] . V[c,:]^T) / rowsum   (rowsum from partials, in-kernel)
    hgemm_k<3, false, false, 32, 5><<<dim3(C / 128, NPIX / 128, BATCH), 256, SM_NN>>>(
        ph, qkvh + (size_t)2 * C * NPIX, nullptr, partial, nullptr, oth,
        NPIX, NPIX, C, NPIX,
        (long long)NPIX * NPIX, (long long)3 * C * NPIX, (long long)NPIX * C);

    // 6) out[o,j] fp32 = Wout[o,c] . OT[j,c]^T + b_out
    hgemm_k<0, false, false, 32, 5><<<dim3(NPIX / 128, C / 128, BATCH), 256, SM_NN>>>(
        woh, oth, b_out, nullptr, nullptr, out, C, C, NPIX, C,
        0LL, (long long)NPIX * C, (long long)C * NPIX);
}